// round 15
// baseline (speedup 1.0000x reference)
#include <cuda_runtime.h>
#include <cuda_fp16.h>
#include <math.h>
#include <stdint.h>

#define BATCH 4
#define SEQ   1024
#define DM    1024
#define NH    16
#define DKH   64

// ---------------- scratch (device globals: allocation-free) ----------------
__device__ float g_xpe [BATCH*SEQ*DM];
__device__ float g_proj[BATCH*SEQ*DM];

__device__ __half g_xh[BATCH*SEQ*DM];
__device__ __half g_qh[BATCH*SEQ*DM];
__device__ __half g_kh[BATCH*SEQ*DM];
__device__ __half g_vth[BATCH*SEQ*DM];
__device__ __half g_ch[BATCH*SEQ*DM];
__device__ __half g_wq[DM*DM], g_wk[DM*DM], g_wv[DM*DM], g_wo[DM*DM];

// Q pre-scale: (1/sqrt(dk)) * log2(e), so attention can use raw ex2
#define QSCALE 0.1803368801111204f

// ---------------- PTX helpers (plain sm_103-safe) ----------------
__device__ __forceinline__ uint32_t smem_u32(const void* p) {
    uint32_t a;
    asm("{ .reg .u64 t; cvta.to.shared.u64 t, %1; cvt.u32.u64 %0, t; }" : "=r"(a) : "l"(p));
    return a;
}
__device__ __forceinline__ float fexp2(float x) {
    float y;
    asm("ex2.approx.ftz.f32 %0, %1;" : "=f"(y) : "f"(x));
    return y;
}

#define LDMATRIX_X4(r0,r1,r2,r3,addr) \
    asm volatile("ldmatrix.sync.aligned.m8n8.x4.shared.b16 {%0,%1,%2,%3}, [%4];" \
                 : "=r"(r0),"=r"(r1),"=r"(r2),"=r"(r3) : "r"(addr))

#define MMA_F16(d0,d1,d2,d3,a0,a1,a2,a3,b0,b1) \
    asm volatile("mma.sync.aligned.m16n8k16.row.col.f32.f16.f16.f32 " \
                 "{%0,%1,%2,%3}, {%4,%5,%6,%7}, {%8,%9}, {%0,%1,%2,%3};" \
                 : "+f"(d0),"+f"(d1),"+f"(d2),"+f"(d3) \
                 : "r"(a0),"r"(a1),"r"(a2),"r"(a3),"r"(b0),"r"(b1))

#define CP_ASYNC16(smem, gptr) \
    asm volatile("cp.async.cg.shared.global [%0], [%1], 16;" :: "r"(smem), "l"(gptr))
#define CP_COMMIT() asm volatile("cp.async.commit_group;")
#define CP_WAIT1()  asm volatile("cp.async.wait_group 1;")
#define CP_WAIT0()  asm volatile("cp.async.wait_group 0;")

__device__ __forceinline__ uint32_t pack2h(float x, float y) {
    __half2 h2 = __floats2half2_rn(x, y);
    return *reinterpret_cast<uint32_t*>(&h2);
}

// ---------------- kernel 1: x + PE -> xpe fp32 AND xh fp16 ----------------
__global__ __launch_bounds__(256) void pe_split(const float* __restrict__ x,
                                                float* __restrict__ xpe,
                                                __half* __restrict__ xh)
{
    int row = blockIdx.x;
    int t   = threadIdx.x;
    int s   = row & (SEQ - 1);
    float pos = (float)s;
    const float C = 9.210340371976184f / 1024.0f;
    size_t base = (size_t)row * DM + t * 4;
    float4 xv = *(const float4*)&x[base];
    int d0 = t * 4;
    float div0 = expf(-C * (float)d0);
    float div1 = expf(-C * (float)(d0 + 2));
    float a0 = pos * div0, a1 = pos * div1;
    float4 o;
    o.x = xv.x + sinf(a0);
    o.y = xv.y + cosf(a0);
    o.z = xv.z + sinf(a1);
    o.w = xv.w + cosf(a1);
    *(float4*)&xpe[base] = o;
    *(uint2*)&xh[base] = make_uint2(pack2h(o.x, o.y), pack2h(o.z, o.w));
}

// ---------------- kernel: 4 weight matrices fp32 -> fp16 in one launch ----------------
__global__ __launch_bounds__(256) void h_convert4(const float* __restrict__ s0,
                                                  const float* __restrict__ s1,
                                                  const float* __restrict__ s2,
                                                  const float* __restrict__ s3,
                                                  __half* __restrict__ d0,
                                                  __half* __restrict__ d1,
                                                  __half* __restrict__ d2,
                                                  __half* __restrict__ d3,
                                                  int n4)
{
    int i = blockIdx.x * 256 + threadIdx.x;
    if (i >= n4) return;
    const float* s; __half* d;
    switch (blockIdx.y) {
        case 0: s = s0; d = d0; break;
        case 1: s = s1; d = d1; break;
        case 2: s = s2; d = d2; break;
        default: s = s3; d = d3; break;
    }
    float4 v = ((const float4*)s)[i];
    ((uint2*)d)[i] = make_uint2(pack2h(v.x, v.y), pack2h(v.z, v.w));
}

// ---------------- GEMM framework: 128x128 tile, 1-term fp16, double-buffered ----------------
#define KCHUNK 64
#define NCHV   (DM / KCHUNK)              // 16
#define ROWB   144                        // 128B data + 16B pad
#define TILE_B (128 * ROWB)               // 18432
#define BUF_B  (2 * TILE_B)               // A, B
#define GEMM_SMEM (2 * BUF_B)             // 73728

template<typename EPI>
__device__ __forceinline__ void gemm_body(const __half* __restrict__ Ah,
                                          const __half* __restrict__ Bh,
                                          int m0, int n0, uint32_t sb, EPI epi)
{
    int t = threadIdx.x;
    int lane = t & 31, wid = t >> 5;
    int warp_m = (wid & 1) * 64;
    int warp_n = (wid >> 1) * 32;

    float acc[4][4][4];
#pragma unroll
    for (int i = 0; i < 4; i++)
#pragma unroll
        for (int j = 0; j < 4; j++)
#pragma unroll
            for (int r = 0; r < 4; r++) acc[i][j][r] = 0.f;

    auto stage = [&](uint32_t bufb, int koff) {
#pragma unroll
        for (int i = 0; i < 4; i++) {
            int id = t + i * 256;
            int r = id >> 3, c = id & 7;
            uint32_t so = r * ROWB + c * 16;
            CP_ASYNC16(bufb + so,          Ah + (size_t)(m0 + r) * DM + koff + c * 8);
            CP_ASYNC16(bufb + TILE_B + so, Bh + (size_t)(n0 + r) * DM + koff + c * 8);
        }
    };

    stage(sb, 0);
    CP_COMMIT();

    int arow = lane & 15;
    int akb  = (lane >> 4) * 16;
    int brow = (lane & 7) + ((lane >> 4) << 3);
    int bkb  = ((lane >> 3) & 1) * 16;

    for (int ch = 0; ch < NCHV; ch++) {
        int buf = ch & 1;
        uint32_t bufb = sb + buf * BUF_B;

        if (ch + 1 < NCHV) {
            stage(sb + ((ch + 1) & 1) * BUF_B, (ch + 1) * KCHUNK);
            CP_COMMIT();
            CP_WAIT1();
        } else {
            CP_WAIT0();
        }
        __syncthreads();

        uint32_t sAh = bufb;
        uint32_t sBh = bufb + TILE_B;

#pragma unroll
        for (int ks = 0; ks < 4; ks++) {
            int kb = ks * 32;
            uint32_t ah[4][4];
#pragma unroll
            for (int mt = 0; mt < 4; mt++) {
                uint32_t off = (uint32_t)((warp_m + mt * 16 + arow) * ROWB + kb + akb);
                LDMATRIX_X4(ah[mt][0], ah[mt][1], ah[mt][2], ah[mt][3], sAh + off);
            }
#pragma unroll
            for (int np = 0; np < 2; np++) {
                uint32_t boff = (uint32_t)((warp_n + np * 16 + brow) * ROWB + kb + bkb);
                uint32_t bh[4];
                LDMATRIX_X4(bh[0], bh[1], bh[2], bh[3], sBh + boff);
#pragma unroll
                for (int hf = 0; hf < 2; hf++) {
                    int nt = np * 2 + hf;
                    uint32_t b0 = bh[hf*2], b1 = bh[hf*2+1];
#pragma unroll
                    for (int mt = 0; mt < 4; mt++) {
                        float* d = acc[mt][nt];
                        MMA_F16(d[0],d[1],d[2],d[3],
                                ah[mt][0],ah[mt][1],ah[mt][2],ah[mt][3], b0,b1);
                    }
                }
            }
        }
        __syncthreads();
    }

    int g  = lane >> 2;
    int tg = lane & 3;
#pragma unroll
    for (int mt = 0; mt < 4; mt++) {
#pragma unroll
        for (int nt = 0; nt < 4; nt++) {
            int row = m0 + warp_m + mt * 16 + g;
            int col = n0 + warp_n + nt * 8 + tg * 2;
            epi(row, col,       acc[mt][nt][0], acc[mt][nt][1]);
            epi(row + 8, col,   acc[mt][nt][2], acc[mt][nt][3]);
        }
    }
}

// ---------------- merged QKV GEMM ----------------
__global__ void __launch_bounds__(256, 2) gemm_qkv(const __half* __restrict__ xh,
                                                   const __half* __restrict__ wq,
                                                   const __half* __restrict__ wk,
                                                   const __half* __restrict__ wv,
                                                   __half* __restrict__ qh,
                                                   __half* __restrict__ kh,
                                                   __half* __restrict__ vth)
{
    extern __shared__ char smem[];
    uint32_t sb = smem_u32(smem);
    int n0g = blockIdx.x * 128;
    int wsel = n0g >> 10;
    int n0 = n0g & (DM - 1);
    int m0 = blockIdx.y * 128;
    const __half* Bh = (wsel == 0) ? wq : (wsel == 1) ? wk : wv;

    if (wsel == 0) {
        gemm_body(xh, Bh, m0, n0, sb, [&](int row, int col, float c0, float c1) {
            *(uint32_t*)&qh[(size_t)row * DM + col] = pack2h(c0 * QSCALE, c1 * QSCALE);
        });
    } else if (wsel == 1) {
        gemm_body(xh, Bh, m0, n0, sb, [&](int row, int col, float c0, float c1) {
            *(uint32_t*)&kh[(size_t)row * DM + col] = pack2h(c0, c1);
        });
    } else {
        gemm_body(xh, Bh, m0, n0, sb, [&](int row, int col, float c0, float c1) {
            int b_ = row >> 10, s_ = row & (SEQ - 1);
            int h_ = col >> 6,  dh = col & 63;
            size_t vbase = (((size_t)(b_ * NH + h_)) * DKH + dh) * SEQ + s_;
            vth[vbase]       = __float2half(c0);
            vth[vbase + SEQ] = __float2half(c1);
        });
    }
}

// ---------------- Wo GEMM (fp32 out) ----------------
__global__ void __launch_bounds__(256, 2) gemm_wo(const __half* __restrict__ ch,
                                                  const __half* __restrict__ wo,
                                                  float* __restrict__ proj)
{
    extern __shared__ char smem[];
    uint32_t sb = smem_u32(smem);
    int m0 = blockIdx.y * 128, n0 = blockIdx.x * 128;
    gemm_body(ch, wo, m0, n0, sb, [&](int row, int col, float c0, float c1) {
        *(float2*)&proj[(size_t)row * DM + col] = make_float2(c0, c1);
    });
}

// ---------------- kernel 3: fp16 mma flash attention, two-pass ----------------
// grid (SEQ/128, NH, BATCH), 128 threads (4 warps x 32 q-rows each).
// Pass 1: scores + rowsums via h2exp2 (f16x2 MUFU, half2 accumulation,
//         fp32 fold each kt). Pass 2: fp32-exact exp, normalized attn
//         stores, PV interleaved per key-block.
#define AROWB 144
#define AMAT  (64 * AROWB)        // 9216
#define QMAT  (128 * AROWB)       // 18432
#define ABUF  (2 * AMAT)          // Kh + Vth per buffer
#define AKV   (sb + QMAT)
#define ATTN_SMEM (QMAT + 2 * ABUF)   // 55296

__global__ void __launch_bounds__(128, 3) attn_mma(
    const __half* __restrict__ qh,
    const __half* __restrict__ kh, const __half* __restrict__ vth,
    float* __restrict__ attn_out,
    __half* __restrict__ cth)
{
    extern __shared__ char smem[];
    uint32_t sb = smem_u32(smem);
    int t = threadIdx.x, lane = t & 31, wid = t >> 5;   // 4 warps
    int q0 = blockIdx.x * 128;
    int h  = blockIdx.y, b = blockIdx.z;
    int g  = lane >> 2, tg = lane & 3;

    size_t qoff = ((size_t)b * SEQ + q0) * DM + h * DKH;
    size_t koff = ((size_t)b * SEQ) * DM + h * DKH;
    size_t voff = ((size_t)(b * NH + h)) * DKH * SEQ;

    // ---- stage Q (128 x 64 fp16) ----
#pragma unroll
    for (int i = 0; i < 8; i++) {
        int id = t + i * 128;
        int r = id >> 3, c = id & 7;
        CP_ASYNC16(sb + r * AROWB + c * 16, qh + qoff + (size_t)r * DM + c * 8);
    }
    CP_COMMIT(); CP_WAIT0();
    __syncthreads();

    uint32_t aqh[2][4][4];
    {
        int arow = lane & 15, akb = (lane >> 4) * 16;
#pragma unroll
        for (int mh = 0; mh < 2; mh++) {
            uint32_t qs = sb + (wid * 32 + mh * 16 + arow) * AROWB + akb;
#pragma unroll
            for (int ks = 0; ks < 4; ks++)
                LDMATRIX_X4(aqh[mh][ks][0], aqh[mh][ks][1], aqh[mh][ks][2], aqh[mh][ks][3],
                            qs + ks * 32);
        }
    }
    __syncthreads();

    int brow = (lane & 7) + ((lane >> 4) << 3);
    int bkb  = ((lane >> 3) & 1) * 16;

    auto load_k = [&](int kt, int buf) {
        uint32_t bb = AKV + buf * ABUF;
#pragma unroll
        for (int i = 0; i < 4; i++) {
            int id = t + i * 128;
            int r = id >> 3, c = id & 7;
            CP_ASYNC16(bb + r * AROWB + c * 16,
                       kh + koff + (size_t)(kt * 64 + r) * DM + c * 8);
        }
    };
    auto load_v = [&](int kt, int buf) {
        uint32_t bb = AKV + buf * ABUF + AMAT;
#pragma unroll
        for (int i = 0; i < 4; i++) {
            int id = t + i * 128;
            int r = id >> 3, c = id & 7;
            CP_ASYNC16(bb + r * AROWB + c * 16,
                       vth + voff + (size_t)r * SEQ + kt * 64 + c * 8);
        }
    };

    // ================= pass 1: rowsums (f16x2 exp) =================
    float lsum[2][2] = {{0.f, 0.f}, {0.f, 0.f}};   // [mh][row g / g+8]
    load_k(0, 0); CP_COMMIT();
    for (int kt = 0; kt < SEQ / 64; kt++) {
        int buf = kt & 1;
        if (kt + 1 < SEQ / 64) { load_k(kt + 1, buf ^ 1); CP_COMMIT(); CP_WAIT1(); }
        else CP_WAIT0();
        __syncthreads();
        uint32_t sKh = AKV + buf * ABUF;

        __half2 hacc[2][2];
#pragma unroll
        for (int mh = 0; mh < 2; mh++)
#pragma unroll
            for (int j = 0; j < 2; j++) hacc[mh][j] = __floats2half2_rn(0.f, 0.f);

#pragma unroll
        for (int np = 0; np < 4; np++) {
            float s_acc[2][2][4];
#pragma unroll
            for (int mh = 0; mh < 2; mh++)
#pragma unroll
                for (int hf = 0; hf < 2; hf++)
#pragma unroll
                    for (int r = 0; r < 4; r++) s_acc[mh][hf][r] = 0.f;
#pragma unroll
            for (int ks = 0; ks < 4; ks++) {
                uint32_t off = (uint32_t)((np * 16 + brow) * AROWB + ks * 32 + bkb);
                uint32_t bh[4];
                LDMATRIX_X4(bh[0], bh[1], bh[2], bh[3], sKh + off);
#pragma unroll
                for (int mh = 0; mh < 2; mh++) {
#pragma unroll
                    for (int hf = 0; hf < 2; hf++) {
                        float* d = s_acc[mh][hf];
                        MMA_F16(d[0],d[1],d[2],d[3],
                                aqh[mh][ks][0],aqh[mh][ks][1],aqh[mh][ks][2],aqh[mh][ks][3],
                                bh[hf*2],bh[hf*2+1]);
                    }
                }
            }
#pragma unroll
            for (int mh = 0; mh < 2; mh++) {
                __half2 e00 = h2exp2(__floats2half2_rn(s_acc[mh][0][0], s_acc[mh][0][1]));
                __half2 e01 = h2exp2(__floats2half2_rn(s_acc[mh][1][0], s_acc[mh][1][1]));
                __half2 e10 = h2exp2(__floats2half2_rn(s_acc[mh][0][2], s_acc[mh][0][3]));
                __half2 e11 = h2exp2(__floats2half2_rn(s_acc[mh][1][2], s_acc[mh][1][3]));
                hacc[mh][0] = __hadd2(hacc[mh][0], __hadd2(e00, e01));
                hacc[mh][1] = __hadd2(hacc[mh][1], __hadd2(e10, e11));
            }
        }
        // fold half2 partials into fp32 once per kt
#pragma unroll
        for (int mh = 0; mh < 2; mh++) {
            float2 f0 = __half22float2(hacc[mh][0]);
            float2 f1 = __half22float2(hacc[mh][1]);
            lsum[mh][0] += f0.x + f0.y;
            lsum[mh][1] += f1.x + f1.y;
        }
        __syncthreads();
    }
    float inv[2][2];
#pragma unroll
    for (int mh = 0; mh < 2; mh++)
#pragma unroll
        for (int j = 0; j < 2; j++) {
            float l = lsum[mh][j];
            l += __shfl_xor_sync(0xffffffffu, l, 1);
            l += __shfl_xor_sync(0xffffffffu, l, 2);
            inv[mh][j] = 1.f / l;
        }

    // ================= pass 2: attn + PV (interleaved per key block) =================
    float o_acc[2][8][4];
#pragma unroll
    for (int mh = 0; mh < 2; mh++)
#pragma unroll
        for (int nt = 0; nt < 8; nt++)
#pragma unroll
            for (int r = 0; r < 4; r++) o_acc[mh][nt][r] = 0.f;

    size_t abase = (((size_t)(b * NH + h)) * SEQ + q0 + wid * 32) * SEQ;

    load_k(0, 0); load_v(0, 0); CP_COMMIT();
    for (int kt = 0; kt < SEQ / 64; kt++) {
        int buf = kt & 1;
        if (kt + 1 < SEQ / 64) { load_k(kt + 1, buf ^ 1); load_v(kt + 1, buf ^ 1); CP_COMMIT(); CP_WAIT1(); }
        else CP_WAIT0();
        __syncthreads();
        uint32_t sKh = AKV + buf * ABUF;
        uint32_t sVh = sKh + AMAT;

#pragma unroll
        for (int np = 0; np < 4; np++) {
            // ---- scores for this 16-key block ----
            float s_acc[2][2][4];
#pragma unroll
            for (int mh = 0; mh < 2; mh++)
#pragma unroll
                for (int hf = 0; hf < 2; hf++)
#pragma unroll
                    for (int r = 0; r < 4; r++) s_acc[mh][hf][r] = 0.f;
#pragma unroll
            for (int ks = 0; ks < 4; ks++) {
                uint32_t off = (uint32_t)((np * 16 + brow) * AROWB + ks * 32 + bkb);
                uint32_t bh[4];
                LDMATRIX_X4(bh[0], bh[1], bh[2], bh[3], sKh + off);
#pragma unroll
                for (int mh = 0; mh < 2; mh++) {
#pragma unroll
                    for (int hf = 0; hf < 2; hf++) {
                        float* d = s_acc[mh][hf];
                        MMA_F16(d[0],d[1],d[2],d[3],
                                aqh[mh][ks][0],aqh[mh][ks][1],aqh[mh][ks][2],aqh[mh][ks][3],
                                bh[hf*2],bh[hf*2+1]);
                    }
                }
            }
            // ---- fp32-exact probabilities + attn stores + P fragments ----
            uint32_t ph[2][4];
#pragma unroll
            for (int mh = 0; mh < 2; mh++)
#pragma unroll
                for (int hf = 0; hf < 2; hf++) {
                    float p0 = fexp2(s_acc[mh][hf][0]) * inv[mh][0];
                    float p1 = fexp2(s_acc[mh][hf][1]) * inv[mh][0];
                    float p2 = fexp2(s_acc[mh][hf][2]) * inv[mh][1];
                    float p3 = fexp2(s_acc[mh][hf][3]) * inv[mh][1];
                    int col = kt * 64 + (np * 2 + hf) * 8 + tg * 2;
                    size_t rbase = abase + (size_t)(mh * 16 + g) * SEQ;
                    *(float2*)&attn_out[rbase + col]           = make_float2(p0, p1);
                    *(float2*)&attn_out[rbase + 8 * SEQ + col] = make_float2(p2, p3);
                    ph[mh][hf * 2 + 0] = pack2h(p0, p1);
                    ph[mh][hf * 2 + 1] = pack2h(p2, p3);
                }
            // ---- PV for this key block (k-step = np) ----
#pragma unroll
            for (int ntb = 0; ntb < 4; ntb++) {
                uint32_t off = (uint32_t)((ntb * 16 + brow) * AROWB + np * 32 + bkb);
                uint32_t bh[4];
                LDMATRIX_X4(bh[0], bh[1], bh[2], bh[3], sVh + off);
#pragma unroll
                for (int mh = 0; mh < 2; mh++) {
#pragma unroll
                    for (int hf = 0; hf < 2; hf++) {
                        float* d = o_acc[mh][ntb * 2 + hf];
                        MMA_F16(d[0],d[1],d[2],d[3],
                                ph[mh][0],ph[mh][1],ph[mh][2],ph[mh][3],
                                bh[hf*2],bh[hf*2+1]);
                    }
                }
            }
        }
        __syncthreads();
    }

    // write ctx as fp16 (hi only)
    size_t cbase = ((size_t)b * SEQ + q0 + wid * 32) * DM + h * DKH;
#pragma unroll
    for (int mh = 0; mh < 2; mh++)
#pragma unroll
        for (int nt = 0; nt < 8; nt++) {
            int col = nt * 8 + tg * 2;
            size_t rbase = cbase + (size_t)(mh * 16 + g) * DM;
            *(uint32_t*)&cth[rbase + col]          = pack2h(o_acc[mh][nt][0], o_acc[mh][nt][1]);
            *(uint32_t*)&cth[rbase + 8 * DM + col] = pack2h(o_acc[mh][nt][2], o_acc[mh][nt][3]);
        }
}

// ---------------- kernel 4: residual + LayerNorm ----------------
__global__ __launch_bounds__(256) void ln_kernel(const float* __restrict__ proj,
                                                 const float* __restrict__ resid,
                                                 const float* __restrict__ gamma,
                                                 const float* __restrict__ beta,
                                                 float* __restrict__ y)
{
    __shared__ float sred[16];
    int row = blockIdx.x;
    int t   = threadIdx.x;
    size_t base = (size_t)row * DM + t * 4;
    float4 pv = *(const float4*)&proj[base];
    float4 rv = *(const float4*)&resid[base];
    float4 vv = make_float4(pv.x+rv.x, pv.y+rv.y, pv.z+rv.z, pv.w+rv.w);
    float s  = vv.x + vv.y + vv.z + vv.w;
    float s2 = vv.x*vv.x + vv.y*vv.y + vv.z*vv.z + vv.w*vv.w;
#pragma unroll
    for (int off = 16; off; off >>= 1) {
        s  += __shfl_xor_sync(0xffffffffu, s,  off);
        s2 += __shfl_xor_sync(0xffffffffu, s2, off);
    }
    int warp = t >> 5, lane = t & 31;
    if (lane == 0) { sred[warp] = s; sred[8 + warp] = s2; }
    __syncthreads();
    if (t == 0) {
        float ts = 0.f, t2 = 0.f;
#pragma unroll
        for (int w = 0; w < 8; w++) { ts += sred[w]; t2 += sred[8 + w]; }
        float mean = ts * (1.0f / DM);
        float var  = t2 * (1.0f / DM) - mean * mean;
        sred[0] = mean;
        sred[1] = rsqrtf(var + 1e-6f);
    }
    __syncthreads();
    float mean = sred[0], rstd = sred[1];
    float4 g4 = *(const float4*)&gamma[t*4];
    float4 b4 = *(const float4*)&beta[t*4];
    float4 o;
    o.x = (vv.x - mean) * rstd * g4.x + b4.x;
    o.y = (vv.y - mean) * rstd * g4.y + b4.y;
    o.z = (vv.z - mean) * rstd * g4.z + b4.z;
    o.w = (vv.w - mean) * rstd * g4.w + b4.w;
    *(float4*)&y[base] = o;
}

// ---------------- launch ----------------
extern "C" void kernel_launch(void* const* d_in, const int* in_sizes, int n_in,
                              void* d_out, int out_size)
{
    const float* x     = (const float*)d_in[0];
    const float* Wq    = (const float*)d_in[1];
    const float* Wk    = (const float*)d_in[2];
    const float* Wv    = (const float*)d_in[3];
    const float* Wo    = (const float*)d_in[4];
    const float* gamma = (const float*)d_in[5];
    const float* beta  = (const float*)d_in[6];

    float* out      = (float*)d_out;
    float* y_out    = out;
    float* attn_out = out + (size_t)BATCH * SEQ * DM;

    float *xpe, *proj;
    cudaGetSymbolAddress((void**)&xpe,  g_xpe);
    cudaGetSymbolAddress((void**)&proj, g_proj);

    __half *xh, *qh, *kh, *vth, *ch, *wq, *wk, *wv, *wo;
    cudaGetSymbolAddress((void**)&xh,  g_xh);
    cudaGetSymbolAddress((void**)&qh,  g_qh);
    cudaGetSymbolAddress((void**)&kh,  g_kh);
    cudaGetSymbolAddress((void**)&vth, g_vth);
    cudaGetSymbolAddress((void**)&ch,  g_ch);
    cudaGetSymbolAddress((void**)&wq,  g_wq);
    cudaGetSymbolAddress((void**)&wk,  g_wk);
    cudaGetSymbolAddress((void**)&wv,  g_wv);
    cudaGetSymbolAddress((void**)&wo,  g_wo);

    cudaFuncSetAttribute((const void*)gemm_qkv,
                         cudaFuncAttributeMaxDynamicSharedMemorySize, GEMM_SMEM);
    cudaFuncSetAttribute((const void*)gemm_wo,
                         cudaFuncAttributeMaxDynamicSharedMemorySize, GEMM_SMEM);
    cudaFuncSetAttribute((const void*)attn_mma,
                         cudaFuncAttributeMaxDynamicSharedMemorySize, ATTN_SMEM);

    const int M = BATCH * SEQ;       // 4096
    const int NW4 = DM * DM / 4;     // 262144

    pe_split<<<M, 256>>>(x, xpe, xh);
    h_convert4<<<dim3(NW4 / 256, 4), 256>>>(Wq, Wk, Wv, Wo, wq, wk, wv, wo, NW4);

    gemm_qkv<<<dim3(3 * DM / 128, M / 128), 256, GEMM_SMEM>>>(xh, wq, wk, wv, qh, kh, vth);

    attn_mma<<<dim3(SEQ / 128, NH, BATCH), 128, ATTN_SMEM>>>(
        qh, kh, vth, attn_out, ch);

    gemm_wo<<<dim3(DM / 128, M / 128), 256, GEMM_SMEM>>>(ch, wo, proj);
    ln_kernel<<<M, 256>>>(proj, xpe, gamma, beta, y_out);
}